// round 11
// baseline (speedup 1.0000x reference)
#include <cuda_runtime.h>
#include <cuda_fp16.h>
#include <cstdint>

// ============================================================================
// FixedSparseLinear: y = x @ W^T + bias
// Densify W to fp16, convert x to fp16, dense GEMM mma.sync.m16n8k16 (f32 acc).
// R11: 4 warps/CTA, warp tile 64x64 -> LDS traffic per MAC cut 33%
// (duplication 2+2 instead of 4+2); 2 CTAs/SM; regs/thread budget 255.
// ============================================================================

#define IN_F   4096
#define OUT_F  4096
#define M_ROWS 8192

#define BM 128
#define BN 128
#define BK 64                 // halves per chunk = 128 bytes = 1 SW128 row
#define NCHUNK (IN_F / BK)    // 64
#define STAGES 3
#define A_STAGE (BM * 128)    // 16384 B
#define B_STAGE (BN * 128)    // 16384 B
#define SMEM_BYTES (1024 + STAGES * (A_STAGE + B_STAGE))  // 99328 -> 2 CTA/SM
#define NTHREADS 128

__device__ __align__(128) __half g_W[(size_t)OUT_F * IN_F];   // 32 MB
__device__ __align__(128) __half g_x[(size_t)M_ROWS * IN_F];  // 64 MB

// ---------------------------------------------------------------------------
__device__ __forceinline__ uint32_t smem_u32(const void* p) {
    uint32_t a;
    asm("{ .reg .u64 t; cvta.to.shared.u64 t, %1; cvt.u32.u64 %0, t; }"
        : "=r"(a) : "l"(p));
    return a;
}

__device__ __forceinline__ uint32_t sw128(uint32_t o) {
    return o ^ ((o >> 3) & 0x70);
}

__device__ __forceinline__ void ldsm_x4(uint32_t* r, uint32_t addr) {
    asm volatile("ldmatrix.sync.aligned.m8n8.x4.shared.b16 {%0,%1,%2,%3}, [%4];"
                 : "=r"(r[0]), "=r"(r[1]), "=r"(r[2]), "=r"(r[3]) : "r"(addr));
}

__device__ __forceinline__ void mma16816(float* c, const uint32_t* a, const uint32_t* b) {
    asm volatile(
        "mma.sync.aligned.m16n8k16.row.col.f32.f16.f16.f32 "
        "{%0,%1,%2,%3}, {%4,%5,%6,%7}, {%8,%9}, {%0,%1,%2,%3};"
        : "+f"(c[0]), "+f"(c[1]), "+f"(c[2]), "+f"(c[3])
        : "r"(a[0]), "r"(a[1]), "r"(a[2]), "r"(a[3]), "r"(b[0]), "r"(b[1]));
}

// ---------------------------------------------------------------------------
// Prologue kernels
// ---------------------------------------------------------------------------
__global__ void zero_w_kernel() {
    uint4* w = reinterpret_cast<uint4*>(g_W);
    int i = blockIdx.x * blockDim.x + threadIdx.x;  // 2097152 uint4s
    w[i] = make_uint4(0u, 0u, 0u, 0u);
}

__global__ void convert_x_kernel(const float* __restrict__ x) {
    int i = blockIdx.x * blockDim.x + threadIdx.x;  // 16777216 pairs
    float a = x[2 * i], b = x[2 * i + 1];
    reinterpret_cast<__half2*>(g_x)[i] = __floats2half2_rn(a, b);
}

// flat_idx sorted, values < 2^24. int64 -> odd words 0; int32 -> words < 2^24.
#define NELEM ((uint32_t)(OUT_F) * (uint32_t)(IN_F))
__device__ __forceinline__ bool words_are_i64idx(const uint32_t* w) {
    return (w[1] == 0u) & (w[3] == 0u) & (w[5] == 0u) & (w[7] == 0u);
}
__device__ __forceinline__ bool words_are_i32idx(const uint32_t* w) {
    bool ok = true;
#pragma unroll
    for (int j = 0; j < 8; ++j) ok &= (w[j] < NELEM);
    return ok;
}

__global__ void scatter_kernel(const uint32_t* __restrict__ A,
                               const uint32_t* __restrict__ B, int nnz) {
    const uint32_t* idxw;
    const float* vals;
    bool is64;
    if (words_are_i64idx(A))        { idxw = A; vals = (const float*)B; is64 = true;  }
    else if (words_are_i64idx(B))   { idxw = B; vals = (const float*)A; is64 = true;  }
    else if (words_are_i32idx(A))   { idxw = A; vals = (const float*)B; is64 = false; }
    else                            { idxw = B; vals = (const float*)A; is64 = false; }

    int i = blockIdx.x * blockDim.x + threadIdx.x;
    if (i < nnz) {
        uint32_t lo = is64 ? idxw[2 * i] : idxw[i];
        uint32_t hi = is64 ? idxw[2 * i + 1] : 0u;
        if (hi == 0u && lo < NELEM) {
            atomicAdd(&g_W[lo], __float2half(vals[i]));
        }
    }
}

// ---------------------------------------------------------------------------
// GEMM: CTA tile [128,128], 128 threads, 4 warps (2m x 2n), warp tile 64x64,
// 3-stage cp.async pipeline, 1 sync per K-chunk.
// ---------------------------------------------------------------------------
__device__ __forceinline__ void load_chunk(uint32_t sa, uint32_t sb_,
                                           const char* ag, const char* bg, int tid) {
#pragma unroll
    for (int it = 0; it < 8; ++it) {   // A: 1024 x 16B @ 128 thr
        int idx = tid + it * NTHREADS;
        int r = idx >> 3, s = idx & 7;
        uint32_t o = (uint32_t)(r * 128 + s * 16);
        asm volatile("cp.async.cg.shared.global [%0], [%1], 16;"
                     :: "r"(sa + sw128(o)), "l"(ag + (size_t)r * 8192 + s * 16));
    }
#pragma unroll
    for (int it = 0; it < 8; ++it) {   // B: 1024 x 16B
        int idx = tid + it * NTHREADS;
        int r = idx >> 3, s = idx & 7;
        uint32_t o = (uint32_t)(r * 128 + s * 16);
        asm volatile("cp.async.cg.shared.global [%0], [%1], 16;"
                     :: "r"(sb_ + sw128(o)), "l"(bg + (size_t)r * 8192 + s * 16));
    }
    asm volatile("cp.async.commit_group;" ::: "memory");
}

__global__ void __launch_bounds__(NTHREADS, 2)
gemm_kernel(const float* __restrict__ bias, float* __restrict__ out) {
    extern __shared__ char smem[];
    const uint32_t sb = smem_u32(smem);
    const int tid = threadIdx.x;
    const int wid = tid >> 5;
    const int lane = tid & 31;
    const int nTile = blockIdx.x;   // 0..31
    const int mTile = blockIdx.y;   // 0..63

    float* bias_s = reinterpret_cast<float*>(smem);
    const uint32_t SA = sb + 1024;
    const uint32_t SB = SA + STAGES * A_STAGE;

    bias_s[tid] = bias[nTile * BN + tid];   // 128 threads cover BN=128

    const int wm = wid & 1;     // rows wm*64..+63
    const int wn = wid >> 1;    // cols wn*64..+63

    const int mat = lane >> 3, l8 = lane & 7;
    const uint32_t aRB = (uint32_t)((wm * 64 + (mat & 1) * 8 + l8) * 128 + (mat >> 1) * 16);
    const uint32_t bRB = (uint32_t)((wn * 64 + (mat >> 1) * 8 + l8) * 128 + (mat & 1) * 16);

    const char* ag = (const char*)g_x + (size_t)mTile * BM * (IN_F * 2);
    const char* bg = (const char*)g_W + (size_t)nTile * BN * (IN_F * 2);

    float acc[4][8][4];
#pragma unroll
    for (int mi = 0; mi < 4; ++mi)
#pragma unroll
        for (int ni = 0; ni < 8; ++ni)
#pragma unroll
            for (int q = 0; q < 4; ++q) acc[mi][ni][q] = 0.f;

#pragma unroll
    for (int s = 0; s < STAGES - 1; ++s)
        load_chunk(SA + s * A_STAGE, SB + s * B_STAGE,
                   ag + (size_t)s * (BK * 2), bg + (size_t)s * (BK * 2), tid);

    for (int c = 0; c < NCHUNK; ++c) {
        asm volatile("cp.async.wait_group %0;" :: "n"(STAGES - 2) : "memory");
        __syncthreads();

        const int cl = c + STAGES - 1;
        if (cl < NCHUNK) {
            const int st = cl % STAGES;
            load_chunk(SA + st * A_STAGE, SB + st * B_STAGE,
                       ag + (size_t)cl * (BK * 2), bg + (size_t)cl * (BK * 2), tid);
        } else {
            asm volatile("cp.async.commit_group;" ::: "memory");
        }

        const uint32_t aBase = SA + (c % STAGES) * A_STAGE;
        const uint32_t bBase = SB + (c % STAGES) * B_STAGE;

#pragma unroll
        for (int ks = 0; ks < 4; ++ks) {
            uint32_t a[4][4], b[4][4];
#pragma unroll
            for (int mi = 0; mi < 4; ++mi)
                ldsm_x4(a[mi], aBase + sw128(aRB + mi * (16 * 128) + ks * 32));
#pragma unroll
            for (int n2 = 0; n2 < 4; ++n2)
                ldsm_x4(b[n2], bBase + sw128(bRB + n2 * (16 * 128) + ks * 32));
#pragma unroll
            for (int mi = 0; mi < 4; ++mi)
#pragma unroll
                for (int ni = 0; ni < 8; ++ni)
                    mma16816(acc[mi][ni], a[mi], &b[ni >> 1][(ni & 1) * 2]);
        }
    }

    // Epilogue: scalar stores.
    const int qid = lane >> 2, tq = lane & 3;
#pragma unroll
    for (int mi = 0; mi < 4; ++mi) {
        const int row0 = mTile * BM + wm * 64 + mi * 16 + qid;
#pragma unroll
        for (int ni = 0; ni < 8; ++ni) {
            const int colL = wn * 64 + ni * 8 + tq * 2;
            const int col = nTile * BN + colL;
            const float b0 = bias_s[colL], b1 = bias_s[colL + 1];
            float* p0 = out + (size_t)row0 * OUT_F + col;
            float* p1 = out + (size_t)(row0 + 8) * OUT_F + col;
            p0[0] = acc[mi][ni][0] + b0;
            p0[1] = acc[mi][ni][1] + b1;
            p1[0] = acc[mi][ni][2] + b0;
            p1[1] = acc[mi][ni][3] + b1;
        }
    }
}

// ---------------------------------------------------------------------------
// kernel_launch — inputs located by element count (order-agnostic):
//   x: 33554432 f32, bias: 4096 f32, {sparse_values | flat_idx}: 1677721
// ---------------------------------------------------------------------------
extern "C" void kernel_launch(void* const* d_in, const int* in_sizes, int n_in,
                              void* d_out, int out_size) {
    int ix = 0, ib = 2, o1 = -1, o2 = -1;
    for (int i = 0; i < n_in; ++i) {
        if (in_sizes[i] == M_ROWS * IN_F)      ix = i;
        else if (in_sizes[i] == OUT_F)         ib = i;
        else if (o1 < 0)                       o1 = i;
        else                                   o2 = i;
    }
    if (o1 < 0) o1 = 1;
    if (o2 < 0) o2 = 3;

    const float* x    = (const float*)d_in[ix];
    const float* bias = (const float*)d_in[ib];
    const int nnz = in_sizes[o1];

    cudaFuncSetAttribute(gemm_kernel, cudaFuncAttributeMaxDynamicSharedMemorySize,
                         SMEM_BYTES);

    zero_w_kernel<<<(OUT_F * IN_F / 8) / 256, 256>>>();
    convert_x_kernel<<<(M_ROWS * IN_F / 2) / 256, 256>>>(x);
    scatter_kernel<<<(nnz + 255) / 256, 256>>>((const uint32_t*)d_in[o1],
                                               (const uint32_t*)d_in[o2], nnz);

    dim3 grid(OUT_F / BN, M_ROWS / BM);  // (32, 64)
    gemm_kernel<<<grid, NTHREADS, SMEM_BYTES>>>(bias, (float*)d_out);
}

// round 14
// speedup vs baseline: 1.0034x; 1.0034x over previous
#include <cuda_runtime.h>
#include <cuda_fp16.h>
#include <cstdint>

// ============================================================================
// FixedSparseLinear: y = x @ W^T + bias
// Densify W to fp16, convert x to fp16, dense GEMM mma.sync.m16n8k16 (f32 acc).
// R14: R13 mbarrier pipeline with the required .noinc on
// cp.async.mbarrier.arrive (plain form is self-balancing -> deadlock).
// Config: 128x128 CTA, 8 warps (4m x 2n), 2 CTA/SM, 3 stages.
// ============================================================================

#define IN_F   4096
#define OUT_F  4096
#define M_ROWS 8192

#define BM 128
#define BN 128
#define BK 64                 // halves per chunk = 128 bytes = 1 SW128 row
#define NCHUNK (IN_F / BK)    // 64
#define STAGES 3
#define A_STAGE (BM * 128)    // 16384 B
#define B_STAGE (BN * 128)    // 16384 B
#define SMEM_BYTES (1024 + STAGES * (A_STAGE + B_STAGE))  // 99328 -> 2 CTA/SM
#define NTHREADS 256

__device__ __align__(128) __half g_W[(size_t)OUT_F * IN_F];   // 32 MB
__device__ __align__(128) __half g_x[(size_t)M_ROWS * IN_F];  // 64 MB

// ---------------------------------------------------------------------------
__device__ __forceinline__ uint32_t smem_u32(const void* p) {
    uint32_t a;
    asm("{ .reg .u64 t; cvta.to.shared.u64 t, %1; cvt.u32.u64 %0, t; }"
        : "=r"(a) : "l"(p));
    return a;
}

__device__ __forceinline__ uint32_t sw128(uint32_t o) {
    return o ^ ((o >> 3) & 0x70);
}

__device__ __forceinline__ void ldsm_x4(uint32_t* r, uint32_t addr) {
    asm volatile("ldmatrix.sync.aligned.m8n8.x4.shared.b16 {%0,%1,%2,%3}, [%4];"
                 : "=r"(r[0]), "=r"(r[1]), "=r"(r[2]), "=r"(r[3]) : "r"(addr));
}

__device__ __forceinline__ void mma16816(float* c, const uint32_t* a, const uint32_t* b) {
    asm volatile(
        "mma.sync.aligned.m16n8k16.row.col.f32.f16.f16.f32 "
        "{%0,%1,%2,%3}, {%4,%5,%6,%7}, {%8,%9}, {%0,%1,%2,%3};"
        : "+f"(c[0]), "+f"(c[1]), "+f"(c[2]), "+f"(c[3])
        : "r"(a[0]), "r"(a[1]), "r"(a[2]), "r"(a[3]), "r"(b[0]), "r"(b[1]));
}

__device__ __forceinline__ void mbar_init(uint32_t mbar, uint32_t cnt) {
    asm volatile("mbarrier.init.shared.b64 [%0], %1;" :: "r"(mbar), "r"(cnt)
                 : "memory");
}

__device__ __forceinline__ void mbar_arrive(uint32_t mbar) {
    asm volatile("mbarrier.arrive.shared::cta.b64 _, [%0];" :: "r"(mbar)
                 : "memory");
}

__device__ __forceinline__ void mbar_wait(uint32_t mbar, uint32_t parity) {
    uint32_t done;
    asm volatile(
        "{ .reg .pred p;\n"
        "  mbarrier.try_wait.parity.acquire.cta.shared::cta.b64 p, [%1], %2;\n"
        "  selp.b32 %0, 1, 0, p; }"
        : "=r"(done) : "r"(mbar), "r"(parity) : "memory");
    while (!done) {
        asm volatile(
            "{ .reg .pred p;\n"
            "  mbarrier.try_wait.parity.acquire.cta.shared::cta.b64 p, [%1], %2, 0x989680;\n"
            "  selp.b32 %0, 1, 0, p; }"
            : "=r"(done) : "r"(mbar), "r"(parity) : "memory");
    }
}

// ---------------------------------------------------------------------------
// Prologue kernels
// ---------------------------------------------------------------------------
__global__ void zero_w_kernel() {
    uint4* w = reinterpret_cast<uint4*>(g_W);
    int i = blockIdx.x * blockDim.x + threadIdx.x;  // 2097152 uint4s
    w[i] = make_uint4(0u, 0u, 0u, 0u);
}

__global__ void convert_x_kernel(const float* __restrict__ x) {
    int i = blockIdx.x * blockDim.x + threadIdx.x;  // 16777216 pairs
    float a = x[2 * i], b = x[2 * i + 1];
    reinterpret_cast<__half2*>(g_x)[i] = __floats2half2_rn(a, b);
}

// flat_idx sorted, values < 2^24. int64 -> odd words 0; int32 -> words < 2^24.
#define NELEM ((uint32_t)(OUT_F) * (uint32_t)(IN_F))
__device__ __forceinline__ bool words_are_i64idx(const uint32_t* w) {
    return (w[1] == 0u) & (w[3] == 0u) & (w[5] == 0u) & (w[7] == 0u);
}
__device__ __forceinline__ bool words_are_i32idx(const uint32_t* w) {
    bool ok = true;
#pragma unroll
    for (int j = 0; j < 8; ++j) ok &= (w[j] < NELEM);
    return ok;
}

__global__ void scatter_kernel(const uint32_t* __restrict__ A,
                               const uint32_t* __restrict__ B, int nnz) {
    const uint32_t* idxw;
    const float* vals;
    bool is64;
    if (words_are_i64idx(A))        { idxw = A; vals = (const float*)B; is64 = true;  }
    else if (words_are_i64idx(B))   { idxw = B; vals = (const float*)A; is64 = true;  }
    else if (words_are_i32idx(A))   { idxw = A; vals = (const float*)B; is64 = false; }
    else                            { idxw = B; vals = (const float*)A; is64 = false; }

    int i = blockIdx.x * blockDim.x + threadIdx.x;
    if (i < nnz) {
        uint32_t lo = is64 ? idxw[2 * i] : idxw[i];
        uint32_t hi = is64 ? idxw[2 * i + 1] : 0u;
        if (hi == 0u && lo < NELEM) {
            atomicAdd(&g_W[lo], __float2half(vals[i]));
        }
    }
}

// ---------------------------------------------------------------------------
// GEMM
// SMEM: [0,512) bias; [512,560) mbarriers (3 full + 3 empty); [1024,...) tiles
// ---------------------------------------------------------------------------
__device__ __forceinline__ void load_chunk(uint32_t sa, uint32_t sb_,
                                           const char* ag, const char* bg,
                                           int tid, uint32_t mbar_full) {
#pragma unroll
    for (int it = 0; it < 4; ++it) {   // A: 1024 x 16B @ 256 thr
        int idx = tid + it * NTHREADS;
        int r = idx >> 3, s = idx & 7;
        uint32_t o = (uint32_t)(r * 128 + s * 16);
        asm volatile("cp.async.cg.shared.global [%0], [%1], 16;"
                     :: "r"(sa + sw128(o)), "l"(ag + (size_t)r * 8192 + s * 16));
    }
#pragma unroll
    for (int it = 0; it < 4; ++it) {   // B: 1024 x 16B
        int idx = tid + it * NTHREADS;
        int r = idx >> 3, s = idx & 7;
        uint32_t o = (uint32_t)(r * 128 + s * 16);
        asm volatile("cp.async.cg.shared.global [%0], [%1], 16;"
                     :: "r"(sb_ + sw128(o)), "l"(bg + (size_t)r * 8192 + s * 16));
    }
    // .noinc: this arrival counts against the init count (256) when all of
    // this thread's prior cp.asyncs complete. (Plain form is self-balancing
    // and would never flip the barrier.)
    asm volatile("cp.async.mbarrier.arrive.noinc.shared::cta.b64 [%0];"
                 :: "r"(mbar_full) : "memory");
}

__global__ void __launch_bounds__(NTHREADS, 2)
gemm_kernel(const float* __restrict__ bias, float* __restrict__ out) {
    extern __shared__ char smem[];
    const uint32_t sb = smem_u32(smem);
    const int tid = threadIdx.x;
    const int wid = tid >> 5;
    const int lane = tid & 31;
    const int nTile = blockIdx.x;   // 0..31
    const int mTile = blockIdx.y;   // 0..63

    float* bias_s = reinterpret_cast<float*>(smem);
    const uint32_t MB_F = sb + 512;          // full[s]  at +512 + 8s
    const uint32_t MB_E = sb + 512 + 24;     // empty[s] at +536 + 8s
    const uint32_t SA = sb + 1024;
    const uint32_t SB = SA + STAGES * A_STAGE;

    if (tid < BN) bias_s[tid] = bias[nTile * BN + tid];
    if (tid == 0) {
#pragma unroll
        for (int s = 0; s < STAGES; ++s) {
            mbar_init(MB_F + 8 * s, NTHREADS);
            mbar_init(MB_E + 8 * s, NTHREADS);
        }
    }
    __syncthreads();   // mbarrier init + bias_s visible to all threads

    const int wm = wid & 3;     // rows wm*32..+31
    const int wn = wid >> 2;    // cols wn*64..+63

    const int mat = lane >> 3, l8 = lane & 7;
    const uint32_t aRB = (uint32_t)((wm * 32 + (mat & 1) * 8 + l8) * 128 + (mat >> 1) * 16);
    const uint32_t bRB = (uint32_t)((wn * 64 + (mat >> 1) * 8 + l8) * 128 + (mat & 1) * 16);

    const char* ag = (const char*)g_x + (size_t)mTile * BM * (IN_F * 2);
    const char* bg = (const char*)g_W + (size_t)nTile * BN * (IN_F * 2);

    float acc[2][8][4];
#pragma unroll
    for (int mi = 0; mi < 2; ++mi)
#pragma unroll
        for (int ni = 0; ni < 8; ++ni)
#pragma unroll
            for (int q = 0; q < 4; ++q) acc[mi][ni][q] = 0.f;

    // Prologue: chunks 0,1 -> stages 0,1
#pragma unroll
    for (int s = 0; s < STAGES - 1; ++s)
        load_chunk(SA + s * A_STAGE, SB + s * B_STAGE,
                   ag + (size_t)s * (BK * 2), bg + (size_t)s * (BK * 2),
                   tid, MB_F + 8 * s);

    uint32_t a[2][2][4], b[2][4][4];   // double-buffered fragments

    for (int c = 0; c < NCHUNK; ++c) {
        // Producer: issue chunk cl into stage cl%3 (after stage is empty).
        const int cl = c + STAGES - 1;
        if (cl < NCHUNK) {
            const int st = cl % STAGES;
            if (cl >= STAGES)
                mbar_wait(MB_E + 8 * st, (uint32_t)(((cl - STAGES) / STAGES) & 1));
            load_chunk(SA + st * A_STAGE, SB + st * B_STAGE,
                       ag + (size_t)cl * (BK * 2), bg + (size_t)cl * (BK * 2),
                       tid, MB_F + 8 * st);
        }

        // Consumer: wait for chunk c's data (cross-thread, acquire).
        mbar_wait(MB_F + 8 * (c % STAGES), (uint32_t)((c / STAGES) & 1));

        const uint32_t aBase = SA + (c % STAGES) * A_STAGE;
        const uint32_t bBase = SB + (c % STAGES) * B_STAGE;

        // Prefetch ks=0 fragments
#pragma unroll
        for (int mi = 0; mi < 2; ++mi)
            ldsm_x4(a[0][mi], aBase + sw128(aRB + mi * (16 * 128)));
#pragma unroll
        for (int n2 = 0; n2 < 4; ++n2)
            ldsm_x4(b[0][n2], bBase + sw128(bRB + n2 * (16 * 128)));

#pragma unroll
        for (int ks = 0; ks < 4; ++ks) {
            const int cur = ks & 1, nxt = cur ^ 1;
            if (ks < 3) {
#pragma unroll
                for (int mi = 0; mi < 2; ++mi)
                    ldsm_x4(a[nxt][mi], aBase + sw128(aRB + mi * (16 * 128) + (ks + 1) * 32));
#pragma unroll
                for (int n2 = 0; n2 < 4; ++n2)
                    ldsm_x4(b[nxt][n2], bBase + sw128(bRB + n2 * (16 * 128) + (ks + 1) * 32));
            }
            if (ks == 2) {
                // Last LDSM of chunk c issued: this stage may be refilled.
                mbar_arrive(MB_E + 8 * (c % STAGES));
            }
#pragma unroll
            for (int mi = 0; mi < 2; ++mi)
#pragma unroll
                for (int ni = 0; ni < 8; ++ni)
                    mma16816(acc[mi][ni], a[cur][mi], &b[cur][ni >> 1][(ni & 1) * 2]);
        }
    }

    // Epilogue: scalar stores (bias_s ordered by the initial __syncthreads).
    const int qid = lane >> 2, tq = lane & 3;
#pragma unroll
    for (int mi = 0; mi < 2; ++mi) {
        const int row0 = mTile * BM + wm * 32 + mi * 16 + qid;
#pragma unroll
        for (int ni = 0; ni < 8; ++ni) {
            const int colL = wn * 64 + ni * 8 + tq * 2;
            const int col = nTile * BN + colL;
            const float b0 = bias_s[colL], b1 = bias_s[colL + 1];
            float* p0 = out + (size_t)row0 * OUT_F + col;
            float* p1 = out + (size_t)(row0 + 8) * OUT_F + col;
            p0[0] = acc[mi][ni][0] + b0;
            p0[1] = acc[mi][ni][1] + b1;
            p1[0] = acc[mi][ni][2] + b0;
            p1[1] = acc[mi][ni][3] + b1;
        }
    }
}

// ---------------------------------------------------------------------------
// kernel_launch — inputs located by element count (order-agnostic):
//   x: 33554432 f32, bias: 4096 f32, {sparse_values | flat_idx}: 1677721
// ---------------------------------------------------------------------------
extern "C" void kernel_launch(void* const* d_in, const int* in_sizes, int n_in,
                              void* d_out, int out_size) {
    int ix = 0, ib = 2, o1 = -1, o2 = -1;
    for (int i = 0; i < n_in; ++i) {
        if (in_sizes[i] == M_ROWS * IN_F)      ix = i;
        else if (in_sizes[i] == OUT_F)         ib = i;
        else if (o1 < 0)                       o1 = i;
        else                                   o2 = i;
    }
    if (o1 < 0) o1 = 1;
    if (o2 < 0) o2 = 3;

    const float* x    = (const float*)d_in[ix];
    const float* bias = (const float*)d_in[ib];
    const int nnz = in_sizes[o1];

    cudaFuncSetAttribute(gemm_kernel, cudaFuncAttributeMaxDynamicSharedMemorySize,
                         SMEM_BYTES);

    zero_w_kernel<<<(OUT_F * IN_F / 8) / 256, 256>>>();
    convert_x_kernel<<<(M_ROWS * IN_F / 2) / 256, 256>>>(x);
    scatter_kernel<<<(nnz + 255) / 256, 256>>>((const uint32_t*)d_in[o1],
                                               (const uint32_t*)d_in[o2], nnz);

    dim3 grid(OUT_F / BN, M_ROWS / BM);  // (32, 64)
    gemm_kernel<<<grid, NTHREADS, SMEM_BYTES>>>(bias, (float*)d_out);
}

// round 15
// speedup vs baseline: 1.0472x; 1.0437x over previous
#include <cuda_runtime.h>
#include <cuda_fp16.h>
#include <cstdint>

// ============================================================================
// FixedSparseLinear: y = x @ W^T + bias
// Densify W to fp16, convert x to fp16, dense GEMM mma.sync.m16n8k16 (f32 acc).
// R15: GEMM = proven-best R10 body (128x128 CTA, 8 warps 4mx2n, 2 CTA/SM,
// 3-stage cp.async, 1 sync/chunk, double-buffered fragments).
// Prologue fused: one kernel zeroes W and converts x (float4-vectorized);
// scatter unchanged in logic.
// ============================================================================

#define IN_F   4096
#define OUT_F  4096
#define M_ROWS 8192

#define BM 128
#define BN 128
#define BK 64                 // halves per chunk = 128 bytes = 1 SW128 row
#define NCHUNK (IN_F / BK)    // 64
#define STAGES 3
#define A_STAGE (BM * 128)    // 16384 B
#define B_STAGE (BN * 128)    // 16384 B
#define SMEM_BYTES (1024 + STAGES * (A_STAGE + B_STAGE))  // 99328 -> 2 CTA/SM
#define NTHREADS 256

__device__ __align__(128) __half g_W[(size_t)OUT_F * IN_F];   // 32 MB
__device__ __align__(128) __half g_x[(size_t)M_ROWS * IN_F];  // 64 MB

// ---------------------------------------------------------------------------
__device__ __forceinline__ uint32_t smem_u32(const void* p) {
    uint32_t a;
    asm("{ .reg .u64 t; cvta.to.shared.u64 t, %1; cvt.u32.u64 %0, t; }"
        : "=r"(a) : "l"(p));
    return a;
}

__device__ __forceinline__ uint32_t sw128(uint32_t o) {
    return o ^ ((o >> 3) & 0x70);
}

__device__ __forceinline__ void ldsm_x4(uint32_t* r, uint32_t addr) {
    asm volatile("ldmatrix.sync.aligned.m8n8.x4.shared.b16 {%0,%1,%2,%3}, [%4];"
                 : "=r"(r[0]), "=r"(r[1]), "=r"(r[2]), "=r"(r[3]) : "r"(addr));
}

__device__ __forceinline__ void mma16816(float* c, const uint32_t* a, const uint32_t* b) {
    asm volatile(
        "mma.sync.aligned.m16n8k16.row.col.f32.f16.f16.f32 "
        "{%0,%1,%2,%3}, {%4,%5,%6,%7}, {%8,%9}, {%0,%1,%2,%3};"
        : "+f"(c[0]), "+f"(c[1]), "+f"(c[2]), "+f"(c[3])
        : "r"(a[0]), "r"(a[1]), "r"(a[2]), "r"(a[3]), "r"(b[0]), "r"(b[1]));
}

// ---------------------------------------------------------------------------
// Fused prologue: blocks [0, ZBLK) zero W (uint4), rest convert x (float4).
// ---------------------------------------------------------------------------
#define ZBLK  8192          // 2097152 uint4s / 256 threads
#define CBLK  32768         // 8388608 float4s / 256 threads

__global__ void prologue_kernel(const float4* __restrict__ x) {
    if (blockIdx.x < ZBLK) {
        int i = blockIdx.x * 256 + threadIdx.x;          // 0 .. 2097151
        reinterpret_cast<uint4*>(g_W)[i] = make_uint4(0u, 0u, 0u, 0u);
    } else {
        int i = (blockIdx.x - ZBLK) * 256 + threadIdx.x; // 0 .. 8388607
        float4 v = x[i];
        uint2 o;
        o.x = __half2_raw(__floats2half2_rn(v.x, v.y)).x |
              ((uint32_t)__half2_raw(__floats2half2_rn(v.x, v.y)).y << 16);
        // simpler: build via half2 stores
        __half2 h0 = __floats2half2_rn(v.x, v.y);
        __half2 h1 = __floats2half2_rn(v.z, v.w);
        uint2 w;
        w.x = *reinterpret_cast<uint32_t*>(&h0);
        w.y = *reinterpret_cast<uint32_t*>(&h1);
        reinterpret_cast<uint2*>(g_x)[i] = w;
    }
}

// flat_idx sorted, values < 2^24. int64 -> odd words 0; int32 -> words < 2^24.
#define NELEM ((uint32_t)(OUT_F) * (uint32_t)(IN_F))
__device__ __forceinline__ bool words_are_i64idx(const uint32_t* w) {
    return (w[1] == 0u) & (w[3] == 0u) & (w[5] == 0u) & (w[7] == 0u);
}
__device__ __forceinline__ bool words_are_i32idx(const uint32_t* w) {
    bool ok = true;
#pragma unroll
    for (int j = 0; j < 8; ++j) ok &= (w[j] < NELEM);
    return ok;
}

__global__ void scatter_kernel(const uint32_t* __restrict__ A,
                               const uint32_t* __restrict__ B, int nnz) {
    const uint32_t* idxw;
    const float* vals;
    bool is64;
    if (words_are_i64idx(A))        { idxw = A; vals = (const float*)B; is64 = true;  }
    else if (words_are_i64idx(B))   { idxw = B; vals = (const float*)A; is64 = true;  }
    else if (words_are_i32idx(A))   { idxw = A; vals = (const float*)B; is64 = false; }
    else                            { idxw = B; vals = (const float*)A; is64 = false; }

    int i = blockIdx.x * blockDim.x + threadIdx.x;
    if (i < nnz) {
        uint32_t lo = is64 ? idxw[2 * i] : idxw[i];
        uint32_t hi = is64 ? idxw[2 * i + 1] : 0u;
        if (hi == 0u && lo < NELEM) {
            atomicAdd(&g_W[lo], __float2half(vals[i]));
        }
    }
}

// ---------------------------------------------------------------------------
// GEMM (R10 body): CTA tile [128,128], 256 threads, 8 warps (4m x 2n),
// warp tile 32x64, 3-stage cp.async, 1 sync/chunk, double-buffered fragments.
// ---------------------------------------------------------------------------
__device__ __forceinline__ void load_chunk(uint32_t sa, uint32_t sb_,
                                           const char* ag, const char* bg, int tid) {
#pragma unroll
    for (int it = 0; it < 4; ++it) {   // A: 1024 x 16B @ 256 thr
        int idx = tid + it * NTHREADS;
        int r = idx >> 3, s = idx & 7;
        uint32_t o = (uint32_t)(r * 128 + s * 16);
        asm volatile("cp.async.cg.shared.global [%0], [%1], 16;"
                     :: "r"(sa + sw128(o)), "l"(ag + (size_t)r * 8192 + s * 16));
    }
#pragma unroll
    for (int it = 0; it < 4; ++it) {   // B: 1024 x 16B
        int idx = tid + it * NTHREADS;
        int r = idx >> 3, s = idx & 7;
        uint32_t o = (uint32_t)(r * 128 + s * 16);
        asm volatile("cp.async.cg.shared.global [%0], [%1], 16;"
                     :: "r"(sb_ + sw128(o)), "l"(bg + (size_t)r * 8192 + s * 16));
    }
    asm volatile("cp.async.commit_group;" ::: "memory");
}

__global__ void __launch_bounds__(NTHREADS, 2)
gemm_kernel(const float* __restrict__ bias, float* __restrict__ out) {
    extern __shared__ char smem[];
    const uint32_t sb = smem_u32(smem);
    const int tid = threadIdx.x;
    const int wid = tid >> 5;
    const int lane = tid & 31;
    const int nTile = blockIdx.x;   // 0..31
    const int mTile = blockIdx.y;   // 0..63

    float* bias_s = reinterpret_cast<float*>(smem);
    const uint32_t SA = sb + 1024;
    const uint32_t SB = SA + STAGES * A_STAGE;

    if (tid < BN) bias_s[tid] = bias[nTile * BN + tid];

    const int wm = wid & 3;     // rows wm*32..+31
    const int wn = wid >> 2;    // cols wn*64..+63

    const int mat = lane >> 3, l8 = lane & 7;
    const uint32_t aRB = (uint32_t)((wm * 32 + (mat & 1) * 8 + l8) * 128 + (mat >> 1) * 16);
    const uint32_t bRB = (uint32_t)((wn * 64 + (mat >> 1) * 8 + l8) * 128 + (mat & 1) * 16);

    const char* ag = (const char*)g_x + (size_t)mTile * BM * (IN_F * 2);
    const char* bg = (const char*)g_W + (size_t)nTile * BN * (IN_F * 2);

    float acc[2][8][4];
#pragma unroll
    for (int mi = 0; mi < 2; ++mi)
#pragma unroll
        for (int ni = 0; ni < 8; ++ni)
#pragma unroll
            for (int q = 0; q < 4; ++q) acc[mi][ni][q] = 0.f;

#pragma unroll
    for (int s = 0; s < STAGES - 1; ++s)
        load_chunk(SA + s * A_STAGE, SB + s * B_STAGE,
                   ag + (size_t)s * (BK * 2), bg + (size_t)s * (BK * 2), tid);

    uint32_t a[2][2][4], b[2][4][4];   // double-buffered fragments

    for (int c = 0; c < NCHUNK; ++c) {
        asm volatile("cp.async.wait_group %0;" :: "n"(STAGES - 2) : "memory");
        __syncthreads();

        const int cl = c + STAGES - 1;
        if (cl < NCHUNK) {
            const int st = cl % STAGES;
            load_chunk(SA + st * A_STAGE, SB + st * B_STAGE,
                       ag + (size_t)cl * (BK * 2), bg + (size_t)cl * (BK * 2), tid);
        } else {
            asm volatile("cp.async.commit_group;" ::: "memory");
        }

        const uint32_t aBase = SA + (c % STAGES) * A_STAGE;
        const uint32_t bBase = SB + (c % STAGES) * B_STAGE;

        // Prefetch ks=0 fragments into buffer 0
#pragma unroll
        for (int mi = 0; mi < 2; ++mi)
            ldsm_x4(a[0][mi], aBase + sw128(aRB + mi * (16 * 128)));
#pragma unroll
        for (int n2 = 0; n2 < 4; ++n2)
            ldsm_x4(b[0][n2], bBase + sw128(bRB + n2 * (16 * 128)));

#pragma unroll
        for (int ks = 0; ks < 4; ++ks) {
            const int cur = ks & 1, nxt = cur ^ 1;
            if (ks < 3) {   // prefetch ks+1 fragments while MMAs of ks run
#pragma unroll
                for (int mi = 0; mi < 2; ++mi)
                    ldsm_x4(a[nxt][mi], aBase + sw128(aRB + mi * (16 * 128) + (ks + 1) * 32));
#pragma unroll
                for (int n2 = 0; n2 < 4; ++n2)
                    ldsm_x4(b[nxt][n2], bBase + sw128(bRB + n2 * (16 * 128) + (ks + 1) * 32));
            }
#pragma unroll
            for (int mi = 0; mi < 2; ++mi)
#pragma unroll
                for (int ni = 0; ni < 8; ++ni)
                    mma16816(acc[mi][ni], a[cur][mi], &b[cur][ni >> 1][(ni & 1) * 2]);
        }
    }

    // Epilogue: scalar stores.
    const int qid = lane >> 2, tq = lane & 3;
#pragma unroll
    for (int mi = 0; mi < 2; ++mi) {
        const int row0 = mTile * BM + wm * 32 + mi * 16 + qid;
#pragma unroll
        for (int ni = 0; ni < 8; ++ni) {
            const int colL = wn * 64 + ni * 8 + tq * 2;
            const int col = nTile * BN + colL;
            const float b0 = bias_s[colL], b1 = bias_s[colL + 1];
            float* p0 = out + (size_t)row0 * OUT_F + col;
            float* p1 = out + (size_t)(row0 + 8) * OUT_F + col;
            p0[0] = acc[mi][ni][0] + b0;
            p0[1] = acc[mi][ni][1] + b1;
            p1[0] = acc[mi][ni][2] + b0;
            p1[1] = acc[mi][ni][3] + b1;
        }
    }
}

// ---------------------------------------------------------------------------
// kernel_launch — inputs located by element count (order-agnostic):
//   x: 33554432 f32, bias: 4096 f32, {sparse_values | flat_idx}: 1677721
// ---------------------------------------------------------------------------
extern "C" void kernel_launch(void* const* d_in, const int* in_sizes, int n_in,
                              void* d_out, int out_size) {
    int ix = 0, ib = 2, o1 = -1, o2 = -1;
    for (int i = 0; i < n_in; ++i) {
        if (in_sizes[i] == M_ROWS * IN_F)      ix = i;
        else if (in_sizes[i] == OUT_F)         ib = i;
        else if (o1 < 0)                       o1 = i;
        else                                   o2 = i;
    }
    if (o1 < 0) o1 = 1;
    if (o2 < 0) o2 = 3;

    const float* x    = (const float*)d_in[ix];
    const float* bias = (const float*)d_in[ib];
    const int nnz = in_sizes[o1];

    cudaFuncSetAttribute(gemm_kernel, cudaFuncAttributeMaxDynamicSharedMemorySize,
                         SMEM_BYTES);

    prologue_kernel<<<ZBLK + CBLK, 256>>>((const float4*)x);
    scatter_kernel<<<(nnz + 255) / 256, 256>>>((const uint32_t*)d_in[o1],
                                               (const uint32_t*)d_in[o2], nnz);

    dim3 grid(OUT_F / BN, M_ROWS / BM);  // (32, 64)
    gemm_kernel<<<grid, NTHREADS, SMEM_BYTES>>>(bias, (float*)d_out);
}

// round 16
// speedup vs baseline: 1.0739x; 1.0255x over previous
#include <cuda_runtime.h>
#include <cuda_fp16.h>
#include <cstdint>

// ============================================================================
// FixedSparseLinear: y = x @ W^T + bias
// Densify W to fp16, convert x to fp16, dense GEMM mma.sync.m16n8k16 (f32 acc).
// R16: zero_w; then ONE kernel doing convert-x (float4) + scatter (block-range
// split); GEMM = proven R10 body; epilogue stores vectorized to float2.
// ============================================================================

#define IN_F   4096
#define OUT_F  4096
#define M_ROWS 8192

#define BM 128
#define BN 128
#define BK 64                 // halves per chunk = 128 bytes = 1 SW128 row
#define NCHUNK (IN_F / BK)    // 64
#define STAGES 3
#define A_STAGE (BM * 128)    // 16384 B
#define B_STAGE (BN * 128)    // 16384 B
#define SMEM_BYTES (1024 + STAGES * (A_STAGE + B_STAGE))  // 99328 -> 2 CTA/SM
#define NTHREADS 256

__device__ __align__(128) __half g_W[(size_t)OUT_F * IN_F];   // 32 MB
__device__ __align__(128) __half g_x[(size_t)M_ROWS * IN_F];  // 64 MB

// ---------------------------------------------------------------------------
__device__ __forceinline__ uint32_t smem_u32(const void* p) {
    uint32_t a;
    asm("{ .reg .u64 t; cvta.to.shared.u64 t, %1; cvt.u32.u64 %0, t; }"
        : "=r"(a) : "l"(p));
    return a;
}

__device__ __forceinline__ uint32_t sw128(uint32_t o) {
    return o ^ ((o >> 3) & 0x70);
}

__device__ __forceinline__ void ldsm_x4(uint32_t* r, uint32_t addr) {
    asm volatile("ldmatrix.sync.aligned.m8n8.x4.shared.b16 {%0,%1,%2,%3}, [%4];"
                 : "=r"(r[0]), "=r"(r[1]), "=r"(r[2]), "=r"(r[3]) : "r"(addr));
}

__device__ __forceinline__ void mma16816(float* c, const uint32_t* a, const uint32_t* b) {
    asm volatile(
        "mma.sync.aligned.m16n8k16.row.col.f32.f16.f16.f32 "
        "{%0,%1,%2,%3}, {%4,%5,%6,%7}, {%8,%9}, {%0,%1,%2,%3};"
        : "+f"(c[0]), "+f"(c[1]), "+f"(c[2]), "+f"(c[3])
        : "r"(a[0]), "r"(a[1]), "r"(a[2]), "r"(a[3]), "r"(b[0]), "r"(b[1]));
}

// ---------------------------------------------------------------------------
// Prologue
// ---------------------------------------------------------------------------
__global__ void zero_w_kernel() {
    uint4* w = reinterpret_cast<uint4*>(g_W);
    int i = blockIdx.x * blockDim.x + threadIdx.x;  // 2097152 uint4s
    w[i] = make_uint4(0u, 0u, 0u, 0u);
}

// flat_idx sorted, values < 2^24. int64 -> odd words 0; int32 -> words < 2^24.
#define NELEM ((uint32_t)(OUT_F) * (uint32_t)(IN_F))
__device__ __forceinline__ bool words_are_i64idx(const uint32_t* w) {
    return (w[1] == 0u) & (w[3] == 0u) & (w[5] == 0u) & (w[7] == 0u);
}
__device__ __forceinline__ bool words_are_i32idx(const uint32_t* w) {
    bool ok = true;
#pragma unroll
    for (int j = 0; j < 8; ++j) ok &= (w[j] < NELEM);
    return ok;
}

// Blocks [0, CBLK): convert x (float4 -> 2x half2). Blocks [CBLK, ...): scatter.
#define CBLK 32768          // 8388608 float4s / 256 threads

__global__ void convert_scatter_kernel(const float4* __restrict__ x,
                                       const uint32_t* __restrict__ A,
                                       const uint32_t* __restrict__ B, int nnz) {
    if (blockIdx.x < CBLK) {
        int i = blockIdx.x * 256 + threadIdx.x;   // 0 .. 8388607
        float4 v = x[i];
        __half2 h0 = __floats2half2_rn(v.x, v.y);
        __half2 h1 = __floats2half2_rn(v.z, v.w);
        uint2 w;
        w.x = *reinterpret_cast<uint32_t*>(&h0);
        w.y = *reinterpret_cast<uint32_t*>(&h1);
        reinterpret_cast<uint2*>(g_x)[i] = w;
    } else {
        const uint32_t* idxw;
        const float* vals;
        bool is64;
        if (words_are_i64idx(A))        { idxw = A; vals = (const float*)B; is64 = true;  }
        else if (words_are_i64idx(B))   { idxw = B; vals = (const float*)A; is64 = true;  }
        else if (words_are_i32idx(A))   { idxw = A; vals = (const float*)B; is64 = false; }
        else                            { idxw = B; vals = (const float*)A; is64 = false; }

        int i = (blockIdx.x - CBLK) * 256 + threadIdx.x;
        if (i < nnz) {
            uint32_t lo = is64 ? idxw[2 * i] : idxw[i];
            uint32_t hi = is64 ? idxw[2 * i + 1] : 0u;
            if (hi == 0u && lo < NELEM) {
                atomicAdd(&g_W[lo], __float2half(vals[i]));
            }
        }
    }
}

// ---------------------------------------------------------------------------
// GEMM (R10 body): CTA tile [128,128], 256 threads, 8 warps (4m x 2n),
// warp tile 32x64, 3-stage cp.async, 1 sync/chunk, double-buffered fragments.
// ---------------------------------------------------------------------------
__device__ __forceinline__ void load_chunk(uint32_t sa, uint32_t sb_,
                                           const char* ag, const char* bg, int tid) {
#pragma unroll
    for (int it = 0; it < 4; ++it) {   // A: 1024 x 16B @ 256 thr
        int idx = tid + it * NTHREADS;
        int r = idx >> 3, s = idx & 7;
        uint32_t o = (uint32_t)(r * 128 + s * 16);
        asm volatile("cp.async.cg.shared.global [%0], [%1], 16;"
                     :: "r"(sa + sw128(o)), "l"(ag + (size_t)r * 8192 + s * 16));
    }
#pragma unroll
    for (int it = 0; it < 4; ++it) {   // B: 1024 x 16B
        int idx = tid + it * NTHREADS;
        int r = idx >> 3, s = idx & 7;
        uint32_t o = (uint32_t)(r * 128 + s * 16);
        asm volatile("cp.async.cg.shared.global [%0], [%1], 16;"
                     :: "r"(sb_ + sw128(o)), "l"(bg + (size_t)r * 8192 + s * 16));
    }
    asm volatile("cp.async.commit_group;" ::: "memory");
}

__global__ void __launch_bounds__(NTHREADS, 2)
gemm_kernel(const float* __restrict__ bias, float* __restrict__ out) {
    extern __shared__ char smem[];
    const uint32_t sb = smem_u32(smem);
    const int tid = threadIdx.x;
    const int wid = tid >> 5;
    const int lane = tid & 31;
    const int nTile = blockIdx.x;   // 0..31
    const int mTile = blockIdx.y;   // 0..63

    float* bias_s = reinterpret_cast<float*>(smem);
    const uint32_t SA = sb + 1024;
    const uint32_t SB = SA + STAGES * A_STAGE;

    if (tid < BN) bias_s[tid] = bias[nTile * BN + tid];

    const int wm = wid & 3;     // rows wm*32..+31
    const int wn = wid >> 2;    // cols wn*64..+63

    const int mat = lane >> 3, l8 = lane & 7;
    const uint32_t aRB = (uint32_t)((wm * 32 + (mat & 1) * 8 + l8) * 128 + (mat >> 1) * 16);
    const uint32_t bRB = (uint32_t)((wn * 64 + (mat >> 1) * 8 + l8) * 128 + (mat & 1) * 16);

    const char* ag = (const char*)g_x + (size_t)mTile * BM * (IN_F * 2);
    const char* bg = (const char*)g_W + (size_t)nTile * BN * (IN_F * 2);

    float acc[2][8][4];
#pragma unroll
    for (int mi = 0; mi < 2; ++mi)
#pragma unroll
        for (int ni = 0; ni < 8; ++ni)
#pragma unroll
            for (int q = 0; q < 4; ++q) acc[mi][ni][q] = 0.f;

#pragma unroll
    for (int s = 0; s < STAGES - 1; ++s)
        load_chunk(SA + s * A_STAGE, SB + s * B_STAGE,
                   ag + (size_t)s * (BK * 2), bg + (size_t)s * (BK * 2), tid);

    uint32_t a[2][2][4], b[2][4][4];   // double-buffered fragments

    for (int c = 0; c < NCHUNK; ++c) {
        asm volatile("cp.async.wait_group %0;" :: "n"(STAGES - 2) : "memory");
        __syncthreads();

        const int cl = c + STAGES - 1;
        if (cl < NCHUNK) {
            const int st = cl % STAGES;
            load_chunk(SA + st * A_STAGE, SB + st * B_STAGE,
                       ag + (size_t)cl * (BK * 2), bg + (size_t)cl * (BK * 2), tid);
        } else {
            asm volatile("cp.async.commit_group;" ::: "memory");
        }

        const uint32_t aBase = SA + (c % STAGES) * A_STAGE;
        const uint32_t bBase = SB + (c % STAGES) * B_STAGE;

        // Prefetch ks=0 fragments into buffer 0
#pragma unroll
        for (int mi = 0; mi < 2; ++mi)
            ldsm_x4(a[0][mi], aBase + sw128(aRB + mi * (16 * 128)));
#pragma unroll
        for (int n2 = 0; n2 < 4; ++n2)
            ldsm_x4(b[0][n2], bBase + sw128(bRB + n2 * (16 * 128)));

#pragma unroll
        for (int ks = 0; ks < 4; ++ks) {
            const int cur = ks & 1, nxt = cur ^ 1;
            if (ks < 3) {   // prefetch ks+1 fragments while MMAs of ks run
#pragma unroll
                for (int mi = 0; mi < 2; ++mi)
                    ldsm_x4(a[nxt][mi], aBase + sw128(aRB + mi * (16 * 128) + (ks + 1) * 32));
#pragma unroll
                for (int n2 = 0; n2 < 4; ++n2)
                    ldsm_x4(b[nxt][n2], bBase + sw128(bRB + n2 * (16 * 128) + (ks + 1) * 32));
            }
#pragma unroll
            for (int mi = 0; mi < 2; ++mi)
#pragma unroll
                for (int ni = 0; ni < 8; ++ni)
                    mma16816(acc[mi][ni], a[cur][mi], &b[cur][ni >> 1][(ni & 1) * 2]);
        }
    }

    // Epilogue: float2 stores (d_out 256B-aligned; col even -> 8B aligned).
    const int qid = lane >> 2, tq = lane & 3;
#pragma unroll
    for (int mi = 0; mi < 2; ++mi) {
        const int row0 = mTile * BM + wm * 32 + mi * 16 + qid;
#pragma unroll
        for (int ni = 0; ni < 8; ++ni) {
            const int colL = wn * 64 + ni * 8 + tq * 2;
            const int col = nTile * BN + colL;
            const float b0 = bias_s[colL], b1 = bias_s[colL + 1];
            float2 v0 = make_float2(acc[mi][ni][0] + b0, acc[mi][ni][1] + b1);
            float2 v1 = make_float2(acc[mi][ni][2] + b0, acc[mi][ni][3] + b1);
            *reinterpret_cast<float2*>(out + (size_t)row0 * OUT_F + col) = v0;
            *reinterpret_cast<float2*>(out + (size_t)(row0 + 8) * OUT_F + col) = v1;
        }
    }
}

// ---------------------------------------------------------------------------
// kernel_launch — inputs located by element count (order-agnostic):
//   x: 33554432 f32, bias: 4096 f32, {sparse_values | flat_idx}: 1677721
// ---------------------------------------------------------------------------
extern "C" void kernel_launch(void* const* d_in, const int* in_sizes, int n_in,
                              void* d_out, int out_size) {
    int ix = 0, ib = 2, o1 = -1, o2 = -1;
    for (int i = 0; i < n_in; ++i) {
        if (in_sizes[i] == M_ROWS * IN_F)      ix = i;
        else if (in_sizes[i] == OUT_F)         ib = i;
        else if (o1 < 0)                       o1 = i;
        else                                   o2 = i;
    }
    if (o1 < 0) o1 = 1;
    if (o2 < 0) o2 = 3;

    const float* x    = (const float*)d_in[ix];
    const float* bias = (const float*)d_in[ib];
    const int nnz = in_sizes[o1];

    cudaFuncSetAttribute(gemm_kernel, cudaFuncAttributeMaxDynamicSharedMemorySize,
                         SMEM_BYTES);

    zero_w_kernel<<<(OUT_F * IN_F / 8) / 256, 256>>>();
    const int sblk = (nnz + 255) / 256;
    convert_scatter_kernel<<<CBLK + sblk, 256>>>((const float4*)x,
                                                 (const uint32_t*)d_in[o1],
                                                 (const uint32_t*)d_in[o2], nnz);

    dim3 grid(OUT_F / BN, M_ROWS / BM);  // (32, 64)
    gemm_kernel<<<grid, NTHREADS, SMEM_BYTES>>>(bias, (float*)d_out);
}